// round 16
// baseline (speedup 1.0000x reference)
#include <cuda_runtime.h>
#include <cstdint>

#define MAXB 64
#define MAXP 8800
#define MAXN 64

// dynamic smem layout for k_select: sv[MAXP] then hist[4][2048]
#define SEL_SMEM (MAXP * 4 + 4 * 2048 * 4)
// dynamic smem for k_fused lse role: 256 anchors x C floats (+ lead pad)
#define FUSED_SMEM ((256 * 21 + 8) * 4)

// ---------------- scratch (device globals; zero-init at load, self-restoring) ----
__device__ int                g_meta[MAXB * MAXP];    // bti | (pos0<<8)
__device__ int                g_ovr[MAXB * MAXP];     // override n+1, 0 = none
__device__ float              g_lse[MAXB * MAXP];     // per-anchor logsumexp
__device__ float              g_lossc[MAXB * MAXP];   // loss_c (0 for pos)
__device__ unsigned long long g_key[MAXB * MAXN];     // per-GT best prior key (0 = none)
__device__ int                g_numpos[MAXB];
__device__ int                g_bdone[MAXB];          // match completion per batch
__device__ int                g_done;                 // select completion
__device__ double             g_acc[3];               // loc, ce_pos, ce_neg

// ---------------- reductions ----------------
__device__ __forceinline__ double warpSumD(double v) {
#pragma unroll
    for (int o = 16; o; o >>= 1) v += __shfl_down_sync(0xFFFFFFFFu, v, o);
    return v;
}
__device__ __forceinline__ int warpSumI(int v) {
#pragma unroll
    for (int o = 16; o; o >>= 1) v += __shfl_down_sync(0xFFFFFFFFu, v, o);
    return v;
}
__device__ __forceinline__ int warpSufI(int v) {
    int lane = threadIdx.x & 31;
#pragma unroll
    for (int o = 1; o < 32; o <<= 1) {
        int t = __shfl_down_sync(0xFFFFFFFFu, v, o);
        if (lane + o < 32) v += t;
    }
    return v;
}

__device__ int blockSumI(int v, int* sh) {
    __syncthreads();
    int lane = threadIdx.x & 31, wid = threadIdx.x >> 5;
    v = warpSumI(v);
    if (lane == 0) sh[wid] = v;
    __syncthreads();
    if (wid == 0) {
        int nw = (blockDim.x + 31) >> 5;
        int x = (lane < nw) ? sh[lane] : 0;
        x = warpSumI(x);
        if (lane == 0) sh[0] = x;
    }
    __syncthreads();
    return sh[0];
}

__device__ double blockSumD(double v, double* sh) {
    __syncthreads();
    int lane = threadIdx.x & 31, wid = threadIdx.x >> 5;
    v = warpSumD(v);
    if (lane == 0) sh[wid] = v;
    __syncthreads();
    if (wid == 0) {
        int nw = (blockDim.x + 31) >> 5;
        double x = (lane < nw) ? sh[lane] : 0.0;
        x = warpSumD(x);
        if (lane == 0) sh[0] = x;
    }
    __syncthreads();
    return sh[0];
}

// ---------------- fused kernel: match role (blocks < GM) + lse role ----------------
// grid: (GM + GL, B) x 256.  GM = ceil(P/512) match tiles, GL = ceil(P/256) lse tiles.

#define GT_ARITH(g, ga, inA, unA, inB, unB)                                    \
    {                                                                          \
        float iw_ = fmaxf(fminf(ax1, (g).z) - fmaxf(ax0, (g).x), 0.0f);        \
        float ih_ = fmaxf(fminf(ay1, (g).w) - fmaxf(ay0, (g).y), 0.0f);        \
        inA = iw_ * ih_;                                                       \
        unA = (ga) + abA - inA;                                                \
        float jw_ = fmaxf(fminf(bx1, (g).z) - fmaxf(bx0, (g).x), 0.0f);        \
        float jh_ = fmaxf(fminf(by1, (g).w) - fmaxf(by0, (g).y), 0.0f);        \
        inB = jw_ * jh_;                                                       \
        unB = (ga) + abB - inB;                                                \
    }

#define GT_ARGMAX(nn, inA, unA, inB, unB)                                      \
    {                                                                          \
        bool hA = inA * bUA > bIA * unA;                                       \
        bIA = hA ? inA : bIA;  bUA = hA ? unA : bUA;  bNA = hA ? (nn) : bNA;   \
        bool hB = inB * bUB > bIB * unB;                                       \
        bIB = hB ? inB : bIB;  bUB = hB ? unB : bUB;  bNB = hB ? (nn) : bNB;   \
    }

#define GT_SLOW(nn, inA, unA, inB, unB, iA, iB)                                \
    if (iA | iB) {                                                             \
        unsigned long long kA = 0ull, kB = 0ull;                               \
        if (iA) {                                                              \
            float iou_ = inA / unA;                                            \
            kA = ((unsigned long long)__float_as_uint(iou_) << 32) |           \
                 (unsigned long long)(0xFFFFFFFFu - (unsigned)pA);             \
        }                                                                      \
        if (iB) {                                                              \
            float iou_ = inB / unB;                                            \
            kB = ((unsigned long long)__float_as_uint(iou_) << 32) |           \
                 (unsigned long long)(0xFFFFFFFFu - (unsigned)pB);             \
        }                                                                      \
        unsigned long long kk = kA > kB ? kA : kB;                             \
        atomicMax(&sh_best[nn], (unsigned int)(kk >> 32));                     \
        atomicMax(&sh_key[nn], kk);                                            \
    }

template <int C>
__global__ void __launch_bounds__(256) k_fused(
        const float* __restrict__ conf,
        const float* __restrict__ priors, const float* __restrict__ labels,
        const int* __restrict__ obj_count, int P, int NMAX, int GM) {
    extern __shared__ float shc[];   // lse role conf tile
    int b = blockIdx.y;
    int tid = threadIdx.x;

    if ((int)blockIdx.x >= GM) {
        // ================= lse role: stream conf tile, store logsumexp =======
        int p0 = (blockIdx.x - GM) * 256;
        int cnt = min(256, P - p0);
        size_t base_byte = ((size_t)b * P + p0) * C * 4;
        size_t gstart = base_byte & ~(size_t)15;
        int lead = (int)((base_byte - gstart) >> 2);
        int nfl = lead + cnt * C;
        int nf4 = nfl >> 2, rem = nfl & 3;
        const float4* s4 = reinterpret_cast<const float4*>((const char*)conf + gstart);
        float4* d4 = reinterpret_cast<float4*>(shc);
        for (int i = tid; i < nf4; i += 256) d4[i] = s4[i];
        if (tid < rem) shc[nf4 * 4 + tid] = ((const float*)s4)[nf4 * 4 + tid];
        __syncthreads();
        int p = p0 + tid;
        if (p < P) {
            const float* vv = shc + lead + tid * C;
            float s = 0.0f;
#pragma unroll
            for (int c = 0; c < C; c++) s += __expf(vv[c]);
            g_lse[(size_t)b * P + p] = __logf(s);
        }
        return;
    }

    // ================= match role (R15 body) =================
    int wid = tid >> 5;
    int pA = blockIdx.x * 512 + tid;
    int pB = pA + 256;
    bool vA = (pA < P), vB = (pB < P);

    __shared__ float4 sh_box[MAXN];
    __shared__ float  sh_area[MAXN];
    __shared__ unsigned long long sh_key[MAXN];
    __shared__ unsigned int sh_best[MAXN];
    __shared__ int s_last;

    int nv = obj_count[b];
    if (nv > NMAX) nv = NMAX;

    for (int n = tid; n < nv; n += 256) {
        const float* g = labels + ((size_t)b * NMAX + n) * 5;
        float x0 = g[0], y0 = g[1], x1 = g[2], y1 = g[3];
        sh_box[n] = make_float4(x0, y0, x1, y1);
        sh_area[n] = (x1 - x0) * (y1 - y0);
        sh_key[n] = 0ull;
        sh_best[n] = 0u;
    }
    __syncthreads();

    float4 prA = vA ? reinterpret_cast<const float4*>(priors)[pA]
                    : make_float4(4.0f, 4.0f, 0.1f, 0.1f);
    float4 prB = vB ? reinterpret_cast<const float4*>(priors)[pB]
                    : make_float4(4.0f, 4.0f, 0.1f, 0.1f);
    float ax0 = prA.x - 0.5f * prA.z, ay0 = prA.y - 0.5f * prA.w;
    float ax1 = prA.x + 0.5f * prA.z, ay1 = prA.y + 0.5f * prA.w;
    float abA = prA.z * prA.w;
    float bx0 = prB.x - 0.5f * prB.z, by0 = prB.y - 0.5f * prB.w;
    float bx1 = prB.x + 0.5f * prB.z, by1 = prB.y + 0.5f * prB.w;
    float abB = prB.z * prB.w;

    float bIA = 0.0f, bUA = 1.0f;  int bNA = 0;
    float bIB = 0.0f, bUB = 1.0f;  int bNB = 0;

    int kstart = (wid * nv) >> 3;

#pragma unroll 1
    for (int pass = 0; pass < 2; pass++) {
        int nlo = pass ? 0 : kstart;
        int nhi = pass ? kstart : nv;
        int n = nlo;
#pragma unroll 1
        for (; n + 2 <= nhi; n += 2) {
            float4 g0 = sh_box[n];
            float ga0 = sh_area[n];
            float4 g1 = sh_box[n + 1];
            float ga1 = sh_area[n + 1];
            float in0A, un0A, in0B, un0B;
            float in1A, un1A, in1B, un1B;
            GT_ARITH(g0, ga0, in0A, un0A, in0B, un0B)
            GT_ARITH(g1, ga1, in1A, un1A, in1B, un1B)
            GT_ARGMAX(n,     in0A, un0A, in0B, un0B)
            GT_ARGMAX(n + 1, in1A, un1A, in1B, un1B)
            float cur0 = __uint_as_float(sh_best[n]);
            float cur1 = __uint_as_float(sh_best[n + 1]);
            bool i0A = in0A > cur0 * un0A, i0B = in0B > cur0 * un0B;
            bool i1A = in1A > cur1 * un1A, i1B = in1B > cur1 * un1B;
            if (__any_sync(0xFFFFFFFFu, i0A | i0B | i1A | i1B)) {
                GT_SLOW(n,     in0A, un0A, in0B, un0B, i0A, i0B)
                GT_SLOW(n + 1, in1A, un1A, in1B, un1B, i1A, i1B)
            }
        }
        if (n < nhi) {
            float4 g0 = sh_box[n];
            float ga0 = sh_area[n];
            float in0A, un0A, in0B, un0B;
            GT_ARITH(g0, ga0, in0A, un0A, in0B, un0B)
            GT_ARGMAX(n, in0A, un0A, in0B, un0B)
            float cur0 = __uint_as_float(sh_best[n]);
            bool i0A = in0A > cur0 * un0A, i0B = in0B > cur0 * un0B;
            if (__any_sync(0xFFFFFFFFu, i0A | i0B)) {
                GT_SLOW(n, in0A, un0A, in0B, un0B, i0A, i0B)
            }
        }
    }

    if (vA) {
        size_t bp = (size_t)b * P + pA;
        bool pos0 = (bIA > 0.0f) && (bIA >= 0.5f * bUA);
        g_meta[bp] = bNA | (pos0 ? 256 : 0);
        g_ovr[bp] = 0;
    }
    if (vB) {
        size_t bp = (size_t)b * P + pB;
        bool pos0 = (bIB > 0.0f) && (bIB >= 0.5f * bUB);
        g_meta[bp] = bNB | (pos0 ? 256 : 0);
        g_ovr[bp] = 0;
    }
    __syncthreads();
    for (int n = tid; n < nv; n += 256)
        if (sh_key[n]) atomicMax(&g_key[(size_t)b * NMAX + n], sh_key[n]);

    if (tid == 0) {
        __threadfence();
        s_last = (atomicAdd(&g_bdone[b], 1) == GM - 1) ? 1 : 0;
    }
    __syncthreads();
    if (s_last) {
        if (tid < nv) {
            unsigned long long key = g_key[(size_t)b * NMAX + tid];
            unsigned int pp = key ? (0xFFFFFFFFu - (unsigned int)(key & 0xFFFFFFFFull)) : 0u;
            atomicMax(&g_ovr[(size_t)b * P + pp], tid + 1);   // last-n wins
            g_key[(size_t)b * NMAX + tid] = 0ull;             // restore
        }
        if (tid == 0) g_bdone[b] = 0;
    }
}

// ---------------- kernel 2: combine lse + match -> losses ----------------
// grid: (ceil(P/512), B) x 256, 2 anchors/thread
template <int C>
__global__ void __launch_bounds__(256) k_post(
        const float* __restrict__ conf, const float* __restrict__ loc,
        const float* __restrict__ priors, const float* __restrict__ labels,
        int P, int NMAX) {
    __shared__ float4 sh_box[MAXN];
    __shared__ float  sh_cls[MAXN];
    int tid = threadIdx.x;
    int b = blockIdx.y;
    int p0 = blockIdx.x * 512;

    for (int n = tid; n < NMAX; n += 256) {
        const float* g = labels + ((size_t)b * NMAX + n) * 5;
        sh_box[n] = make_float4(g[0], g[1], g[2], g[3]);
        sh_cls[n] = g[4];
    }
    __syncthreads();

    double myloc = 0.0, myce = 0.0;
    int mypos = 0;

#pragma unroll
    for (int half = 0; half < 2; half++) {
        int p = p0 + tid + half * 256;
        if (p >= P) break;
        size_t bp = (size_t)b * P + p;

        int ovr = g_ovr[bp];
        int meta = g_meta[bp];
        int n;  bool pos;
        if (ovr > 0) { n = ovr - 1; pos = true; }
        else         { n = meta & 255; pos = (meta & 256) != 0; }
        int ct = pos ? ((int)sh_cls[n] + 1) : 0;

        float ce = g_lse[bp] - __ldg(conf + bp * C + ct);
        g_lossc[bp] = pos ? 0.0f : ce;

        if (pos) {
            mypos++;
            myce += (double)ce;
            float4 pr = reinterpret_cast<const float4*>(priors)[p];
            float4 g = sh_box[n];
            float t0 = ((g.x + g.z) * 0.5f - pr.x) / (0.1f * pr.z);
            float t1 = ((g.y + g.w) * 0.5f - pr.y) / (0.1f * pr.w);
            float t2 = __logf((g.z - g.x) / pr.z) / 0.2f;
            float t3 = __logf((g.w - g.y) / pr.w) / 0.2f;
            float4 lr = reinterpret_cast<const float4*>(loc)[bp];
            float t[4] = {t0, t1, t2, t3};
            float l[4] = {lr.x, lr.y, lr.z, lr.w};
            float acc = 0.0f;
#pragma unroll
            for (int i = 0; i < 4; i++) {
                float d = fabsf(l[i] - t[i]);
                acc += (d < 1.0f) ? 0.5f * d * d : d - 0.5f;
            }
            myloc += (double)acc;
        }
    }

    __shared__ double shd0[8], shd1[8];
    __shared__ int shi[8];
    int lane = tid & 31, wid = tid >> 5;
    myloc = warpSumD(myloc);
    myce = warpSumD(myce);
    mypos = warpSumI(mypos);
    if (lane == 0) { shd0[wid] = myloc; shd1[wid] = myce; shi[wid] = mypos; }
    __syncthreads();
    if (tid == 0) {
        double a = 0.0, c2 = 0.0; int cp = 0;
        for (int w = 0; w < 8; w++) { a += shd0[w]; c2 += shd1[w]; cp += shi[w]; }
        if (a != 0.0) atomicAdd(&g_acc[0], a);
        if (c2 != 0.0) atomicAdd(&g_acc[1], c2);
        if (cp) atomicAdd(&g_numpos[b], cp);
    }
}

// ---------------- kernel 3: 2-round radix select, 4-replica hist (dynamic smem) ----
// grid: B blocks x 1024, SEL_SMEM dynamic bytes
__global__ void k_select(float* __restrict__ out, int P, int B) {
    extern __shared__ char dynsm[];
    unsigned int* sv = reinterpret_cast<unsigned int*>(dynsm);            // [MAXP]
    int (*hist)[2048] = reinterpret_cast<int(*)[2048]>(dynsm + MAXP * 4); // [4][2048]
    int* hflat = &hist[0][0];

    __shared__ int warpTot[32];
    __shared__ int s_ri[32];
    __shared__ double s_rd[32];
    __shared__ int s_sel;

    int b = blockIdx.x;
    int tid = threadIdx.x, nt = blockDim.x;
    int lane = tid & 31, wid = tid >> 5;

    for (int i = tid; i < P; i += nt)
        sv[i] = __float_as_uint(g_lossc[(size_t)b * P + i]);

    int npos = g_numpos[b];
    int k = 3 * npos;
    if (k > P - 1) k = P - 1;
    __syncthreads();

    if (k > 0) {
        unsigned int prefix = 0;
        int kk = k;
        int iters = (P + nt - 1) / nt;

        for (int r = 0; r < 2; r++) {
            int shift = r ? 10 : 21;
            for (int i = tid; i < 8192; i += nt) hflat[i] = 0;
            if (tid == 0) s_sel = 0;
            __syncthreads();

            int rep = wid & 3;
            for (int j = 0; j < iters; j++) {
                int i = tid + j * nt;
                bool val = (i < P);
                unsigned int v = val ? sv[i] : 0u;
                if (r) val = val && ((v >> 21) == prefix);
                unsigned int bm = __ballot_sync(0xFFFFFFFFu, val);
                if (val) {
                    int bin = (v >> shift) & 2047;
                    unsigned int mm = __match_any_sync(bm, bin);
                    if (lane == __ffs(mm) - 1) atomicAdd(&hist[rep][bin], __popc(mm));
                }
            }
            __syncthreads();

            int h0 = hist[0][2 * tid] + hist[1][2 * tid] + hist[2][2 * tid] + hist[3][2 * tid];
            int h1 = hist[0][2 * tid + 1] + hist[1][2 * tid + 1]
                   + hist[2][2 * tid + 1] + hist[3][2 * tid + 1];
            int v2 = h0 + h1;
            int sIncl = warpSufI(v2);
            if (lane == 0) warpTot[wid] = sIncl;
            __syncthreads();
            if (wid == 0) {
                int t = warpTot[lane];
                int ws = warpSufI(t);
                warpTot[lane] = ws - t;
            }
            __syncthreads();
            int E = (sIncl - v2) + warpTot[wid];
            int suf1 = E + h1, suf0 = suf1 + h0;
            hist[0][2 * tid] = suf0; hist[0][2 * tid + 1] = suf1;
            int cand = -1;
            if (suf1 >= kk) cand = 2 * tid + 1;
            else if (suf0 >= kk) cand = 2 * tid;
            if (cand >= 0) atomicMax(&s_sel, cand);
            __syncthreads();
            int d = s_sel;
            int above = (d + 1 < 2048) ? hist[0][d + 1] : 0;
            kk -= above;
            prefix = (prefix << 11) | (unsigned int)d;
            __syncthreads();
        }

        unsigned int T = prefix << 10;   // threshold exact to 22 bits (validated)
        int c1 = 0;
        double ssum = 0.0;
        for (int i = tid; i < P; i += nt) {
            unsigned int v = sv[i];
            if (v > T) { c1++; ssum += (double)__uint_as_float(v); }
        }
        c1 = blockSumI(c1, s_ri);
        ssum = blockSumD(ssum, s_rd);
        if (tid == 0)
            atomicAdd(&g_acc[2], ssum + (double)(k - c1) * (double)__uint_as_float(T));
    }

    if (tid == 0) {
        __threadfence();
        if (atomicAdd(&g_done, 1) == (int)gridDim.x - 1) {
            long long N = 0;
            for (int bb = 0; bb < B; bb++) N += __ldcg(&g_numpos[bb]);
            double Nd = (double)N;
            double a0 = __ldcg(&g_acc[0]);
            double a1 = __ldcg(&g_acc[1]);
            double a2 = __ldcg(&g_acc[2]);
            out[0] = (float)(a0 / Nd);
            out[1] = (float)((a1 + a2) / Nd);
            for (int bb = 0; bb < B; bb++) g_numpos[bb] = 0;
            g_acc[0] = 0.0; g_acc[1] = 0.0; g_acc[2] = 0.0;
            g_done = 0;
        }
    }
}

// ---------------- launch ----------------
extern "C" void kernel_launch(void* const* d_in, const int* in_sizes, int n_in,
                              void* d_out, int out_size) {
    const float* conf   = (const float*)d_in[0];
    const float* loc    = (const float*)d_in[1];
    const float* priors = (const float*)d_in[2];
    const float* labels = (const float*)d_in[3];
    const int*   obj    = (const int*)d_in[4];

    int P = in_sizes[2] / 4;
    int B = in_sizes[4];
    int NMAX = in_sizes[3] / (B * 5);

    static int smem_set = 0;
    if (!smem_set) {
        cudaFuncSetAttribute(k_select, cudaFuncAttributeMaxDynamicSharedMemorySize,
                             SEL_SMEM);
        smem_set = 1;
    }

    int GM = (P + 511) / 512;
    int GL = (P + 255) / 256;
    dim3 gf(GM + GL, B);
    k_fused<21><<<gf, 256, FUSED_SMEM>>>(conf, priors, labels, obj, P, NMAX, GM);

    dim3 gp((P + 511) / 512, B);
    k_post<21><<<gp, 256>>>(conf, loc, priors, labels, P, NMAX);

    k_select<<<B, 1024, SEL_SMEM>>>((float*)d_out, P, B);
}